// round 1
// baseline (speedup 1.0000x reference)
#include <cuda_runtime.h>
#include <cuda_bf16.h>

// Problem constants
#define HD   128
#define LNUM 2
#define NN   256
#define EE   10000
#define ETN  11
#define NPAIR (LNUM*ETN)          // 22
#define NSEG (NPAIR*NN)           // 5632
#define TOTE (NPAIR*EE)           // 220000

// EDGE_TYPES src/dst as node-type ids: 0=SB,1=PQ,2=PV,3=NB
__constant__ int c_src[ETN] = {0,2,3,1,1,1,2,3,2,1,3};
__constant__ int c_dst[ETN] = {1,1,1,3,0,2,3,2,2,1,3};
// P buffer offset for each pair p=l*11+t (concat order: [SB|PQ|PV|NB], blocks in (l, t) order within dst type)
__constant__ int c_pairOff[NPAIR] = {
  // l=0: t0..t10
  20000, 30000, 40000, 160000, 0, 100000, 170000, 110000, 120000, 50000, 180000,
  // l=1: t0..t10
  60000, 70000, 80000, 190000, 10000, 130000, 200000, 140000, 150000, 90000, 210000
};

// Scratch (device globals; no allocations allowed)
__device__ float    g_coef[NPAIR][23];
__device__ float    g_logit[TOTE];
__device__ float    g_vsum[TOTE];
__device__ unsigned g_m[NSEG];
__device__ int      g_first[NSEG];
__device__ float    g_den[NSEG];
__device__ float    g_num[NSEG];
__device__ float    g_P[TOTE];

// Order-preserving float<->uint encoding for atomicMax on floats
__device__ __forceinline__ unsigned enc_f(float f) {
    unsigned u = __float_as_uint(f);
    return (u & 0x80000000u) ? ~u : (u | 0x80000000u);
}
__device__ __forceinline__ float dec_f(unsigned u) {
    return (u & 0x80000000u) ? __uint_as_float(u & 0x7fffffffu) : __uint_as_float(~u);
}

__device__ __forceinline__ const float* selx(int nt, const float* a, const float* b,
                                             const float* c, const float* d) {
    return nt == 0 ? a : (nt == 1 ? b : (nt == 2 ? c : d));
}

// ---------------------------------------------------------------------------
// 1) Per-(l,t) coefficient precompute: 3x5 bilinear Gram matrix for the logit,
//    row-sum collapse for v (cv[5]) and skip (cs[3]).
// ---------------------------------------------------------------------------
__global__ void coef_kernel(const float* __restrict__ Wq, const float* __restrict__ bq,
                            const float* __restrict__ Wk, const float* __restrict__ bk,
                            const float* __restrict__ Wv, const float* __restrict__ bv,
                            const float* __restrict__ We,
                            const float* __restrict__ Ws, const float* __restrict__ bs) {
    int p = blockIdx.x;       // p = l*ETN + t directly indexes [L,ET,...] arrays
    int h = threadIdx.x;      // 0..127
    float wq0 = Wq[(p*2+0)*HD+h], wq1 = Wq[(p*2+1)*HD+h], bqv = bq[p*HD+h];
    float wk0 = Wk[(p*2+0)*HD+h], wk1 = Wk[(p*2+1)*HD+h], bkv = bk[p*HD+h];
    float we0 = We[(p*2+0)*HD+h], we1 = We[(p*2+1)*HD+h];
    float wv0 = Wv[(p*2+0)*HD+h], wv1 = Wv[(p*2+1)*HD+h], bvv = bv[p*HD+h];
    float ws0 = Ws[(p*2+0)*HD+h], ws1 = Ws[(p*2+1)*HD+h], bsv = bs[p*HD+h];

    float av[3] = {wq0, wq1, bqv};
    float bb[5] = {wk0, wk1, bkv, we0, we1};
    float vals[23];
#pragma unroll
    for (int a = 0; a < 3; a++)
#pragma unroll
        for (int b = 0; b < 5; b++) vals[a*5+b] = av[a]*bb[b];
    vals[15]=wv0; vals[16]=wv1; vals[17]=bvv; vals[18]=we0; vals[19]=we1;
    vals[20]=ws0; vals[21]=ws1; vals[22]=bsv;

    __shared__ float sh[4][23];
    int lane = h & 31, w = h >> 5;
#pragma unroll
    for (int i = 0; i < 23; i++) {
        float v = vals[i];
#pragma unroll
        for (int o = 16; o; o >>= 1) v += __shfl_down_sync(0xffffffffu, v, o);
        if (lane == 0) sh[w][i] = v;
    }
    __syncthreads();
    if (h < 23) g_coef[p][h] = sh[0][h] + sh[1][h] + sh[2][h] + sh[3][h];
}

// ---------------------------------------------------------------------------
// 2) init segment state
// ---------------------------------------------------------------------------
__global__ void init_kernel() {
    int i = blockIdx.x * blockDim.x + threadIdx.x;
    if (i < NSEG) {
        g_m[i] = 0x007fffffu;      // enc(-inf)
        g_first[i] = 0x7fffffff;
        g_den[i] = 0.f;
        g_num[i] = 0.f;
    }
}

// ---------------------------------------------------------------------------
// 3) per-edge logit + Vsum; segment max + first via atomics
// ---------------------------------------------------------------------------
__global__ void logit_kernel(const float* __restrict__ xSB, const float* __restrict__ xPQ,
                             const float* __restrict__ xPV, const float* __restrict__ xNB,
                             const int* __restrict__ ei, const float* __restrict__ ea) {
    int p = blockIdx.y, t = p % ETN;
    int e = blockIdx.x * blockDim.x + threadIdx.x;
    if (e >= EE) return;
    int s = ei[(t*2+0)*EE + e];
    int d = ei[(t*2+1)*EE + e];
    const float* xsrc = selx(c_src[t], xSB, xPQ, xPV, xNB);
    const float* xdst = selx(c_dst[t], xSB, xPQ, xPV, xNB);
    float xs0 = xsrc[s*4+2], xs1 = xsrc[s*4+3];
    float xt0 = xdst[d*4+2], xt1 = xdst[d*4+3];
    float ea0 = ea[(t*EE+e)*2+0], ea1 = ea[(t*EE+e)*2+1];
    const float* C = g_coef[p];
    float r0 = C[0]*xs0 + C[1]*xs1 + C[2] + C[3]*ea0 + C[4]*ea1;
    float r1 = C[5]*xs0 + C[6]*xs1 + C[7] + C[8]*ea0 + C[9]*ea1;
    float r2 = C[10]*xs0 + C[11]*xs1 + C[12] + C[13]*ea0 + C[14]*ea1;
    float logit = (xt0*r0 + xt1*r1 + r2) * 0.08838834764831845f;  // 1/sqrt(128)
    float vs = xs0*C[15] + xs1*C[16] + C[17] + ea0*C[18] + ea1*C[19];
    int idx = p*EE + e;
    g_logit[idx] = logit;
    g_vsum[idx] = vs;
    int si = p*NN + d;
    atomicMax(&g_m[si], enc_f(logit));
    atomicMin(&g_first[si], e);
}

// ---------------------------------------------------------------------------
// 4) exp + segment sums (denominator and numerator = sum exp*Vsum)
// ---------------------------------------------------------------------------
__global__ void expsum_kernel(const int* __restrict__ ei) {
    int p = blockIdx.y, t = p % ETN;
    int e = blockIdx.x * blockDim.x + threadIdx.x;
    if (e >= EE) return;
    int d = ei[(t*2+1)*EE + e];
    int si = p*NN + d;
    int idx = p*EE + e;
    float m = dec_f(g_m[si]);
    float ex = __expf(g_logit[idx] - m);
    atomicAdd(&g_den[si], ex);
    atomicAdd(&g_num[si], ex * g_vsum[idx]);
}

// ---------------------------------------------------------------------------
// 5) per-edge P value: agg lands only at first edge of each dst; + skip rowsum
// ---------------------------------------------------------------------------
__global__ void pval_kernel(const float* __restrict__ xSB, const float* __restrict__ xPQ,
                            const float* __restrict__ xPV, const float* __restrict__ xNB,
                            const int* __restrict__ ei) {
    int p = blockIdx.y, t = p % ETN;
    int e = blockIdx.x * blockDim.x + threadIdx.x;
    if (e >= EE) return;
    int d = ei[(t*2+1)*EE + e];
    const float* xdst = selx(c_dst[t], xSB, xPQ, xPV, xNB);
    float xt0 = xdst[d*4+2], xt1 = xdst[d*4+3];
    const float* C = g_coef[p];
    float v = xt0*C[20] + xt1*C[21] + C[22];
    int si = p*NN + d;
    if (g_first[si] == e) v += g_num[si] / g_den[si];
    g_P[c_pairOff[p] + e] = v;
}

// ---------------------------------------------------------------------------
// 6) FC matvec: out[r] = fcb[r] + sum_i fcW[r, 2i] * P[i]   (odd cols hit zeros)
//    One block per output row (2048 rows total). DRAM-bound: ~901 MB of fcW.
// ---------------------------------------------------------------------------
__global__ void __launch_bounds__(256) fc_kernel(
    const float* __restrict__ W0, const float* __restrict__ W1,
    const float* __restrict__ W2, const float* __restrict__ W3,
    const float* __restrict__ B0, const float* __restrict__ B1,
    const float* __restrict__ B2, const float* __restrict__ B3,
    float* __restrict__ out) {
    int bid = blockIdx.x;
    int nt = bid >> 9;
    int r = bid & 511;
    const float* W = selx(nt, W0, W1, W2, W3);
    const float* B = selx(nt, B0, B1, B2, B3);
    const int nf4arr[4] = {10000, 40000, 30000, 30000};  // fan_in/4 per node type
    const int poff[4]   = {0, 20000, 100000, 160000};
    int nf4 = nf4arr[nt];
    const float4* __restrict__ Wr = (const float4*)W + (size_t)r * nf4;
    const float2* __restrict__ P2 = (const float2*)(g_P + poff[nt]);

    float acc = 0.f;
    int j = threadIdx.x;
#pragma unroll 4
    for (; j < nf4; j += 256) {
        float4 w = Wr[j];
        float2 pv = __ldg(&P2[j]);
        acc = fmaf(w.x, pv.x, fmaf(w.z, pv.y, acc));
    }
#pragma unroll
    for (int o = 16; o; o >>= 1) acc += __shfl_down_sync(0xffffffffu, acc, o);
    __shared__ float sh[8];
    if ((threadIdx.x & 31) == 0) sh[threadIdx.x >> 5] = acc;
    __syncthreads();
    if (threadIdx.x == 0) {
        float s = 0.f;
#pragma unroll
        for (int w = 0; w < 8; w++) s += sh[w];
        out[bid] = s + B[r];
    }
}

// ---------------------------------------------------------------------------
extern "C" void kernel_launch(void* const* d_in, const int* in_sizes, int n_in,
                              void* d_out, int out_size) {
    const float* xSB = (const float*)d_in[0];
    const float* xPQ = (const float*)d_in[1];
    const float* xPV = (const float*)d_in[2];
    const float* xNB = (const float*)d_in[3];
    const int*   ei  = (const int*)d_in[4];
    const float* ea  = (const float*)d_in[5];

    const float *Wq, *Wk, *Wv, *We, *Ws, *bq, *bk, *bv, *bs;
    if (in_sizes[7] == LNUM*ETN*HD) {
        // signature order: Wq, bq, Wk, bk, Wv, bv, We, Wskip, bskip
        Wq = (const float*)d_in[6];  bq = (const float*)d_in[7];
        Wk = (const float*)d_in[8];  bk = (const float*)d_in[9];
        Wv = (const float*)d_in[10]; bv = (const float*)d_in[11];
        We = (const float*)d_in[12];
        Ws = (const float*)d_in[13]; bs = (const float*)d_in[14];
    } else {
        // setup_inputs dict order: Wq, Wk, Wv, We, Wskip, bq, bk, bv, bskip
        Wq = (const float*)d_in[6];
        Wk = (const float*)d_in[7];
        Wv = (const float*)d_in[8];
        We = (const float*)d_in[9];
        Ws = (const float*)d_in[10];
        bq = (const float*)d_in[11];
        bk = (const float*)d_in[12];
        bv = (const float*)d_in[13];
        bs = (const float*)d_in[14];
    }
    const float* fcW_SB = (const float*)d_in[15];
    const float* fcb_SB = (const float*)d_in[16];
    const float* fcW_PQ = (const float*)d_in[17];
    const float* fcb_PQ = (const float*)d_in[18];
    const float* fcW_PV = (const float*)d_in[19];
    const float* fcb_PV = (const float*)d_in[20];
    const float* fcW_NB = (const float*)d_in[21];
    const float* fcb_NB = (const float*)d_in[22];
    float* out = (float*)d_out;

    coef_kernel<<<NPAIR, HD>>>(Wq, bq, Wk, bk, Wv, bv, We, Ws, bs);
    init_kernel<<<(NSEG + 255) / 256, 256>>>();
    dim3 eg((EE + 255) / 256, NPAIR);
    logit_kernel<<<eg, 256>>>(xSB, xPQ, xPV, xNB, ei, ea);
    expsum_kernel<<<eg, 256>>>(ei);
    pval_kernel<<<eg, 256>>>(xSB, xPQ, xPV, xNB, ei);
    fc_kernel<<<2048, 256>>>(fcW_SB, fcW_PQ, fcW_PV, fcW_NB,
                             fcb_SB, fcb_PQ, fcb_PV, fcb_NB, out);
}